// round 4
// baseline (speedup 1.0000x reference)
#include <cuda_runtime.h>
#include <math.h>

#define B_  8
#define T_  2048
#define D_  512

#define BM 128
#define BN 128
#define BK 16
#define NT 256
#define PAD 4   // shared row padding (keeps 16B alignment: (128+4)*4 = 528 bytes)

// Scratch (allocation-free rule: __device__ globals)
__device__ float g_QP[B_ * T_ * D_];
__device__ float g_KP[B_ * T_ * D_];
__device__ float g_VP[B_ * T_ * D_];
__device__ float g_S [(size_t)B_ * T_ * T_];

// ---------------------------------------------------------------------------
// Projection: C[m,n] = sum_k X[m,k] * W[n,k] + bias[n]
// M = B*T = 16384, N = K = 512. NT gemm (both operands K-contiguous).
// which: 0 -> g_QP, 1 -> g_KP, 2 -> g_VP
// ---------------------------------------------------------------------------
__global__ __launch_bounds__(NT) void proj_kernel(
    const float* __restrict__ X, const float* __restrict__ W,
    const float* __restrict__ bias, int which)
{
    const int K = D_, N = D_;
    float* C = (which == 0) ? g_QP : (which == 1) ? g_KP : g_VP;

    __shared__ float As[BK][BM + PAD];
    __shared__ float Bs[BK][BN + PAD];

    const int tid = threadIdx.x;
    const int bm  = blockIdx.x * BM;
    const int bn  = blockIdx.y * BN;
    const int tx  = tid & 15;
    const int ty  = tid >> 4;

    float acc[8][8];
#pragma unroll
    for (int i = 0; i < 8; i++)
#pragma unroll
        for (int j = 0; j < 8; j++) acc[i][j] = 0.f;

    const float* Ag = X + (size_t)bm * K;
    const float* Bg = W + (size_t)bn * K;

    for (int k0 = 0; k0 < K; k0 += BK) {
#pragma unroll
        for (int i = 0; i < 2; i++) {
            int idx = tid + i * NT;
            int r = idx >> 2;
            int c = (idx & 3) * 4;
            float4 a = *(const float4*)(Ag + (size_t)r * K + k0 + c);
            As[c + 0][r] = a.x; As[c + 1][r] = a.y;
            As[c + 2][r] = a.z; As[c + 3][r] = a.w;
            float4 b = *(const float4*)(Bg + (size_t)r * K + k0 + c);
            Bs[c + 0][r] = b.x; Bs[c + 1][r] = b.y;
            Bs[c + 2][r] = b.z; Bs[c + 3][r] = b.w;
        }
        __syncthreads();
#pragma unroll
        for (int kk = 0; kk < BK; kk++) {
            float4 a0 = *(const float4*)&As[kk][ty * 4];
            float4 a1 = *(const float4*)&As[kk][64 + ty * 4];
            float4 b0 = *(const float4*)&Bs[kk][tx * 4];
            float4 b1 = *(const float4*)&Bs[kk][64 + tx * 4];
            float ra[8] = {a0.x, a0.y, a0.z, a0.w, a1.x, a1.y, a1.z, a1.w};
            float rb[8] = {b0.x, b0.y, b0.z, b0.w, b1.x, b1.y, b1.z, b1.w};
#pragma unroll
            for (int i = 0; i < 8; i++)
#pragma unroll
                for (int j = 0; j < 8; j++)
                    acc[i][j] = fmaf(ra[i], rb[j], acc[i][j]);
        }
        __syncthreads();
    }

#pragma unroll
    for (int ih = 0; ih < 2; ih++) {
#pragma unroll
        for (int ii = 0; ii < 4; ii++) {
            int m = bm + ih * 64 + ty * 4 + ii;
            int ai = ih * 4 + ii;
#pragma unroll
            for (int jh = 0; jh < 2; jh++) {
                int n = bn + jh * 64 + tx * 4;
                float4 bz = *(const float4*)(bias + n);
                float4 o;
                o.x = acc[ai][jh * 4 + 0] + bz.x;
                o.y = acc[ai][jh * 4 + 1] + bz.y;
                o.z = acc[ai][jh * 4 + 2] + bz.z;
                o.w = acc[ai][jh * 4 + 3] + bz.w;
                *(float4*)(C + (size_t)m * N + n) = o;
            }
        }
    }
}

// ---------------------------------------------------------------------------
// Scores: S[b,m,n] = (sum_k QP[b,m,k] * KP[b,n,k]) * scale * mask[b,m,n]
// Per-batch NT gemm, M = N = T_, K = D_.
// ---------------------------------------------------------------------------
__global__ __launch_bounds__(NT) void score_kernel(
    const float* __restrict__ mask)
{
    const int K = D_, N = T_;
    const float scale = 0.04419417382415922f;  // 1/sqrt(512)

    const int b = blockIdx.z;
    const float* Ag = g_QP + (size_t)b * T_ * D_ + (size_t)blockIdx.x * BM * K;
    const float* Bg = g_KP + (size_t)b * T_ * D_ + (size_t)blockIdx.y * BN * K;
    const float* Mg = mask + (size_t)b * T_ * T_;
    float*       Cg = g_S  + (size_t)b * T_ * T_;

    __shared__ float As[BK][BM + PAD];
    __shared__ float Bs[BK][BN + PAD];

    const int tid = threadIdx.x;
    const int tx  = tid & 15;
    const int ty  = tid >> 4;

    float acc[8][8];
#pragma unroll
    for (int i = 0; i < 8; i++)
#pragma unroll
        for (int j = 0; j < 8; j++) acc[i][j] = 0.f;

    for (int k0 = 0; k0 < K; k0 += BK) {
#pragma unroll
        for (int i = 0; i < 2; i++) {
            int idx = tid + i * NT;
            int r = idx >> 2;
            int c = (idx & 3) * 4;
            float4 a = *(const float4*)(Ag + (size_t)r * K + k0 + c);
            As[c + 0][r] = a.x; As[c + 1][r] = a.y;
            As[c + 2][r] = a.z; As[c + 3][r] = a.w;
            float4 bv = *(const float4*)(Bg + (size_t)r * K + k0 + c);
            Bs[c + 0][r] = bv.x; Bs[c + 1][r] = bv.y;
            Bs[c + 2][r] = bv.z; Bs[c + 3][r] = bv.w;
        }
        __syncthreads();
#pragma unroll
        for (int kk = 0; kk < BK; kk++) {
            float4 a0 = *(const float4*)&As[kk][ty * 4];
            float4 a1 = *(const float4*)&As[kk][64 + ty * 4];
            float4 b0 = *(const float4*)&Bs[kk][tx * 4];
            float4 b1 = *(const float4*)&Bs[kk][64 + tx * 4];
            float ra[8] = {a0.x, a0.y, a0.z, a0.w, a1.x, a1.y, a1.z, a1.w};
            float rb[8] = {b0.x, b0.y, b0.z, b0.w, b1.x, b1.y, b1.z, b1.w};
#pragma unroll
            for (int i = 0; i < 8; i++)
#pragma unroll
                for (int j = 0; j < 8; j++)
                    acc[i][j] = fmaf(ra[i], rb[j], acc[i][j]);
        }
        __syncthreads();
    }

    const int bm = blockIdx.x * BM;
    const int bn = blockIdx.y * BN;
#pragma unroll
    for (int ih = 0; ih < 2; ih++) {
#pragma unroll
        for (int ii = 0; ii < 4; ii++) {
            int m = bm + ih * 64 + ty * 4 + ii;
            int ai = ih * 4 + ii;
#pragma unroll
            for (int jh = 0; jh < 2; jh++) {
                int n = bn + jh * 64 + tx * 4;
                float4 mk = *(const float4*)(Mg + (size_t)m * N + n);
                float4 o;
                o.x = acc[ai][jh * 4 + 0] * scale * mk.x;
                o.y = acc[ai][jh * 4 + 1] * scale * mk.y;
                o.z = acc[ai][jh * 4 + 2] * scale * mk.z;
                o.w = acc[ai][jh * 4 + 3] * scale * mk.w;
                *(float4*)(Cg + (size_t)m * N + n) = o;
            }
        }
    }
}

// ---------------------------------------------------------------------------
// Row softmax over g_S: one CTA per row (B*T rows, T_ cols).
// Each thread holds its 8 values in registers: 1 read + 1 write per element.
// ---------------------------------------------------------------------------
__global__ __launch_bounds__(NT) void softmax_kernel()
{
    float* p = g_S + (size_t)blockIdx.x * T_;
    const int tid = threadIdx.x;

    float4 a = *(const float4*)(p + tid * 4);
    float4 b = *(const float4*)(p + 1024 + tid * 4);

    float m = fmaxf(fmaxf(fmaxf(a.x, a.y), fmaxf(a.z, a.w)),
                    fmaxf(fmaxf(b.x, b.y), fmaxf(b.z, b.w)));

    __shared__ float red[NT];
    red[tid] = m;
    __syncthreads();
#pragma unroll
    for (int s = NT / 2; s > 0; s >>= 1) {
        if (tid < s) red[tid] = fmaxf(red[tid], red[tid + s]);
        __syncthreads();
    }
    float rowmax = red[0];
    __syncthreads();

    a.x = __expf(a.x - rowmax); a.y = __expf(a.y - rowmax);
    a.z = __expf(a.z - rowmax); a.w = __expf(a.w - rowmax);
    b.x = __expf(b.x - rowmax); b.y = __expf(b.y - rowmax);
    b.z = __expf(b.z - rowmax); b.w = __expf(b.w - rowmax);

    float s8 = (a.x + a.y) + (a.z + a.w) + (b.x + b.y) + (b.z + b.w);
    red[tid] = s8;
    __syncthreads();
#pragma unroll
    for (int s = NT / 2; s > 0; s >>= 1) {
        if (tid < s) red[tid] += red[tid + s];
        __syncthreads();
    }
    float inv = 1.0f / red[0];

    a.x *= inv; a.y *= inv; a.z *= inv; a.w *= inv;
    b.x *= inv; b.y *= inv; b.z *= inv; b.w *= inv;
    *(float4*)(p + tid * 4) = a;
    *(float4*)(p + 1024 + tid * 4) = b;
}

// ---------------------------------------------------------------------------
// Output: O[b,m,n] = sum_k P[b,m,k] * VP[b,k,n]
// Per-batch NN gemm, M = T_, N = D_, K = T_. P K-contiguous, V N-contiguous.
// ---------------------------------------------------------------------------
__global__ __launch_bounds__(NT) void pv_kernel(float* __restrict__ out)
{
    const int K = T_, N = D_;

    const int b = blockIdx.z;
    const float* Ag = g_S  + (size_t)b * T_ * T_ + (size_t)blockIdx.x * BM * K;
    const float* Bg = g_VP + (size_t)b * T_ * D_;
    float*       Cg = out  + (size_t)b * T_ * D_;

    __shared__ float As[BK][BM + PAD];
    __shared__ float Bs[BK][BN + PAD];

    const int tid = threadIdx.x;
    const int bn  = blockIdx.y * BN;
    const int tx  = tid & 15;
    const int ty  = tid >> 4;

    float acc[8][8];
#pragma unroll
    for (int i = 0; i < 8; i++)
#pragma unroll
        for (int j = 0; j < 8; j++) acc[i][j] = 0.f;

    for (int k0 = 0; k0 < K; k0 += BK) {
        // A tile: 128 rows x 16 k (K-contiguous), transposed into As
#pragma unroll
        for (int i = 0; i < 2; i++) {
            int idx = tid + i * NT;
            int r = idx >> 2;
            int c = (idx & 3) * 4;
            float4 a = *(const float4*)(Ag + (size_t)r * K + k0 + c);
            As[c + 0][r] = a.x; As[c + 1][r] = a.y;
            As[c + 2][r] = a.z; As[c + 3][r] = a.w;
        }
        // B tile: 16 k-rows x 128 n (N-contiguous), direct
#pragma unroll
        for (int i = 0; i < 2; i++) {
            int idx = tid + i * NT;
            int kr = idx >> 5;
            int c4 = idx & 31;
            float4 vv = *(const float4*)(Bg + (size_t)(k0 + kr) * N + bn + c4 * 4);
            *(float4*)&Bs[kr][c4 * 4] = vv;
        }
        __syncthreads();
#pragma unroll
        for (int kk = 0; kk < BK; kk++) {
            float4 a0 = *(const float4*)&As[kk][ty * 4];
            float4 a1 = *(const float4*)&As[kk][64 + ty * 4];
            float4 b0 = *(const float4*)&Bs[kk][tx * 4];
            float4 b1 = *(const float4*)&Bs[kk][64 + tx * 4];
            float ra[8] = {a0.x, a0.y, a0.z, a0.w, a1.x, a1.y, a1.z, a1.w};
            float rb[8] = {b0.x, b0.y, b0.z, b0.w, b1.x, b1.y, b1.z, b1.w};
#pragma unroll
            for (int i = 0; i < 8; i++)
#pragma unroll
                for (int j = 0; j < 8; j++)
                    acc[i][j] = fmaf(ra[i], rb[j], acc[i][j]);
        }
        __syncthreads();
    }

    const int bm = blockIdx.x * BM;
#pragma unroll
    for (int ih = 0; ih < 2; ih++) {
#pragma unroll
        for (int ii = 0; ii < 4; ii++) {
            int m = bm + ih * 64 + ty * 4 + ii;
            int ai = ih * 4 + ii;
#pragma unroll
            for (int jh = 0; jh < 2; jh++) {
                int n = bn + jh * 64 + tx * 4;
                float4 o;
                o.x = acc[ai][jh * 4 + 0];
                o.y = acc[ai][jh * 4 + 1];
                o.z = acc[ai][jh * 4 + 2];
                o.w = acc[ai][jh * 4 + 3];
                *(float4*)(Cg + (size_t)m * N + n) = o;
            }
        }
    }
}

// ---------------------------------------------------------------------------
// Launch
// ---------------------------------------------------------------------------
extern "C" void kernel_launch(void* const* d_in, const int* in_sizes, int n_in,
                              void* d_out, int out_size)
{
    const float* q    = (const float*)d_in[0];
    const float* k    = (const float*)d_in[1];
    const float* v    = (const float*)d_in[2];
    const float* Wq   = (const float*)d_in[3];
    const float* bq   = (const float*)d_in[4];
    const float* Wk   = (const float*)d_in[5];
    const float* bk   = (const float*)d_in[6];
    const float* Wv   = (const float*)d_in[7];
    const float* bv   = (const float*)d_in[8];
    const float* mask = (const float*)d_in[9];
    float* out = (float*)d_out;

    // 1) Projections: M = B*T = 16384, N = 512
    dim3 gp((B_ * T_) / BM, D_ / BN);
    proj_kernel<<<gp, NT>>>(q, Wq, bq, 0);
    proj_kernel<<<gp, NT>>>(k, Wk, bk, 1);
    proj_kernel<<<gp, NT>>>(v, Wv, bv, 2);

    // 2) Scores (scale + mask fused in epilogue)
    dim3 gs(T_ / BM, T_ / BN, B_);
    score_kernel<<<gs, NT>>>(mask);

    // 3) Row softmax
    softmax_kernel<<<B_ * T_, NT>>>();

    // 4) O = P @ V
    dim3 go(T_ / BM, D_ / BN, B_);
    pv_kernel<<<go, NT>>>(out);
}

// round 5
// speedup vs baseline: 1.0004x; 1.0004x over previous
#include <cuda_runtime.h>
#include <math.h>

#define B_  8
#define T_  2048
#define D_  512

#define BM 128
#define BN 128
#define BK 16
#define NT 256
#define PAD 4   // shared row padding (keeps 16B alignment: (128+4)*4 = 528 bytes)

// Scratch (allocation-free rule: __device__ globals)
__device__ float g_QP[B_ * T_ * D_];
__device__ float g_KP[B_ * T_ * D_];
__device__ float g_VP[B_ * T_ * D_];
__device__ float g_S [(size_t)B_ * T_ * T_];

// ---------------------------------------------------------------------------
// Projection: C[m,n] = sum_k X[m,k] * W[n,k] + bias[n]
// M = B*T = 16384, N = K = 512. NT gemm (both operands K-contiguous).
// which: 0 -> g_QP, 1 -> g_KP, 2 -> g_VP
// ---------------------------------------------------------------------------
__global__ __launch_bounds__(NT) void proj_kernel(
    const float* __restrict__ X, const float* __restrict__ W,
    const float* __restrict__ bias, int which)
{
    const int K = D_, N = D_;
    float* C = (which == 0) ? g_QP : (which == 1) ? g_KP : g_VP;

    __shared__ float As[BK][BM + PAD];
    __shared__ float Bs[BK][BN + PAD];

    const int tid = threadIdx.x;
    const int bm  = blockIdx.x * BM;
    const int bn  = blockIdx.y * BN;
    const int tx  = tid & 15;
    const int ty  = tid >> 4;

    float acc[8][8];
#pragma unroll
    for (int i = 0; i < 8; i++)
#pragma unroll
        for (int j = 0; j < 8; j++) acc[i][j] = 0.f;

    const float* Ag = X + (size_t)bm * K;
    const float* Bg = W + (size_t)bn * K;

    for (int k0 = 0; k0 < K; k0 += BK) {
#pragma unroll
        for (int i = 0; i < 2; i++) {
            int idx = tid + i * NT;
            int r = idx >> 2;
            int c = (idx & 3) * 4;
            float4 a = *(const float4*)(Ag + (size_t)r * K + k0 + c);
            As[c + 0][r] = a.x; As[c + 1][r] = a.y;
            As[c + 2][r] = a.z; As[c + 3][r] = a.w;
            float4 b = *(const float4*)(Bg + (size_t)r * K + k0 + c);
            Bs[c + 0][r] = b.x; Bs[c + 1][r] = b.y;
            Bs[c + 2][r] = b.z; Bs[c + 3][r] = b.w;
        }
        __syncthreads();
#pragma unroll
        for (int kk = 0; kk < BK; kk++) {
            float4 a0 = *(const float4*)&As[kk][ty * 4];
            float4 a1 = *(const float4*)&As[kk][64 + ty * 4];
            float4 b0 = *(const float4*)&Bs[kk][tx * 4];
            float4 b1 = *(const float4*)&Bs[kk][64 + tx * 4];
            float ra[8] = {a0.x, a0.y, a0.z, a0.w, a1.x, a1.y, a1.z, a1.w};
            float rb[8] = {b0.x, b0.y, b0.z, b0.w, b1.x, b1.y, b1.z, b1.w};
#pragma unroll
            for (int i = 0; i < 8; i++)
#pragma unroll
                for (int j = 0; j < 8; j++)
                    acc[i][j] = fmaf(ra[i], rb[j], acc[i][j]);
        }
        __syncthreads();
    }

#pragma unroll
    for (int ih = 0; ih < 2; ih++) {
#pragma unroll
        for (int ii = 0; ii < 4; ii++) {
            int m = bm + ih * 64 + ty * 4 + ii;
            int ai = ih * 4 + ii;
#pragma unroll
            for (int jh = 0; jh < 2; jh++) {
                int n = bn + jh * 64 + tx * 4;
                float4 bz = *(const float4*)(bias + n);
                float4 o;
                o.x = acc[ai][jh * 4 + 0] + bz.x;
                o.y = acc[ai][jh * 4 + 1] + bz.y;
                o.z = acc[ai][jh * 4 + 2] + bz.z;
                o.w = acc[ai][jh * 4 + 3] + bz.w;
                *(float4*)(C + (size_t)m * N + n) = o;
            }
        }
    }
}

// ---------------------------------------------------------------------------
// Scores: S[b,m,n] = (sum_k QP[b,m,k] * KP[b,n,k]) * scale * mask[b,m,n]
// Per-batch NT gemm, M = N = T_, K = D_.
// ---------------------------------------------------------------------------
__global__ __launch_bounds__(NT) void score_kernel(
    const float* __restrict__ mask)
{
    const int K = D_, N = T_;
    const float scale = 0.04419417382415922f;  // 1/sqrt(512)

    const int b = blockIdx.z;
    const float* Ag = g_QP + (size_t)b * T_ * D_ + (size_t)blockIdx.x * BM * K;
    const float* Bg = g_KP + (size_t)b * T_ * D_ + (size_t)blockIdx.y * BN * K;
    const float* Mg = mask + (size_t)b * T_ * T_;
    float*       Cg = g_S  + (size_t)b * T_ * T_;

    __shared__ float As[BK][BM + PAD];
    __shared__ float Bs[BK][BN + PAD];

    const int tid = threadIdx.x;
    const int tx  = tid & 15;
    const int ty  = tid >> 4;

    float acc[8][8];
#pragma unroll
    for (int i = 0; i < 8; i++)
#pragma unroll
        for (int j = 0; j < 8; j++) acc[i][j] = 0.f;

    for (int k0 = 0; k0 < K; k0 += BK) {
#pragma unroll
        for (int i = 0; i < 2; i++) {
            int idx = tid + i * NT;
            int r = idx >> 2;
            int c = (idx & 3) * 4;
            float4 a = *(const float4*)(Ag + (size_t)r * K + k0 + c);
            As[c + 0][r] = a.x; As[c + 1][r] = a.y;
            As[c + 2][r] = a.z; As[c + 3][r] = a.w;
            float4 bv = *(const float4*)(Bg + (size_t)r * K + k0 + c);
            Bs[c + 0][r] = bv.x; Bs[c + 1][r] = bv.y;
            Bs[c + 2][r] = bv.z; Bs[c + 3][r] = bv.w;
        }
        __syncthreads();
#pragma unroll
        for (int kk = 0; kk < BK; kk++) {
            float4 a0 = *(const float4*)&As[kk][ty * 4];
            float4 a1 = *(const float4*)&As[kk][64 + ty * 4];
            float4 b0 = *(const float4*)&Bs[kk][tx * 4];
            float4 b1 = *(const float4*)&Bs[kk][64 + tx * 4];
            float ra[8] = {a0.x, a0.y, a0.z, a0.w, a1.x, a1.y, a1.z, a1.w};
            float rb[8] = {b0.x, b0.y, b0.z, b0.w, b1.x, b1.y, b1.z, b1.w};
#pragma unroll
            for (int i = 0; i < 8; i++)
#pragma unroll
                for (int j = 0; j < 8; j++)
                    acc[i][j] = fmaf(ra[i], rb[j], acc[i][j]);
        }
        __syncthreads();
    }

    const int bm = blockIdx.x * BM;
    const int bn = blockIdx.y * BN;
#pragma unroll
    for (int ih = 0; ih < 2; ih++) {
#pragma unroll
        for (int ii = 0; ii < 4; ii++) {
            int m = bm + ih * 64 + ty * 4 + ii;
            int ai = ih * 4 + ii;
#pragma unroll
            for (int jh = 0; jh < 2; jh++) {
                int n = bn + jh * 64 + tx * 4;
                float4 mk = *(const float4*)(Mg + (size_t)m * N + n);
                float4 o;
                o.x = acc[ai][jh * 4 + 0] * scale * mk.x;
                o.y = acc[ai][jh * 4 + 1] * scale * mk.y;
                o.z = acc[ai][jh * 4 + 2] * scale * mk.z;
                o.w = acc[ai][jh * 4 + 3] * scale * mk.w;
                *(float4*)(Cg + (size_t)m * N + n) = o;
            }
        }
    }
}

// ---------------------------------------------------------------------------
// Row softmax over g_S: one CTA per row (B*T rows, T_ cols).
// Each thread holds its 8 values in registers: 1 read + 1 write per element.
// ---------------------------------------------------------------------------
__global__ __launch_bounds__(NT) void softmax_kernel()
{
    float* p = g_S + (size_t)blockIdx.x * T_;
    const int tid = threadIdx.x;

    float4 a = *(const float4*)(p + tid * 4);
    float4 b = *(const float4*)(p + 1024 + tid * 4);

    float m = fmaxf(fmaxf(fmaxf(a.x, a.y), fmaxf(a.z, a.w)),
                    fmaxf(fmaxf(b.x, b.y), fmaxf(b.z, b.w)));

    __shared__ float red[NT];
    red[tid] = m;
    __syncthreads();
#pragma unroll
    for (int s = NT / 2; s > 0; s >>= 1) {
        if (tid < s) red[tid] = fmaxf(red[tid], red[tid + s]);
        __syncthreads();
    }
    float rowmax = red[0];
    __syncthreads();

    a.x = __expf(a.x - rowmax); a.y = __expf(a.y - rowmax);
    a.z = __expf(a.z - rowmax); a.w = __expf(a.w - rowmax);
    b.x = __expf(b.x - rowmax); b.y = __expf(b.y - rowmax);
    b.z = __expf(b.z - rowmax); b.w = __expf(b.w - rowmax);

    float s8 = (a.x + a.y) + (a.z + a.w) + (b.x + b.y) + (b.z + b.w);
    red[tid] = s8;
    __syncthreads();
#pragma unroll
    for (int s = NT / 2; s > 0; s >>= 1) {
        if (tid < s) red[tid] += red[tid + s];
        __syncthreads();
    }
    float inv = 1.0f / red[0];

    a.x *= inv; a.y *= inv; a.z *= inv; a.w *= inv;
    b.x *= inv; b.y *= inv; b.z *= inv; b.w *= inv;
    *(float4*)(p + tid * 4) = a;
    *(float4*)(p + 1024 + tid * 4) = b;
}

// ---------------------------------------------------------------------------
// Output: O[b,m,n] = sum_k P[b,m,k] * VP[b,k,n]
// Per-batch NN gemm, M = T_, N = D_, K = T_. P K-contiguous, V N-contiguous.
// ---------------------------------------------------------------------------
__global__ __launch_bounds__(NT) void pv_kernel(float* __restrict__ out)
{
    const int K = T_, N = D_;

    const int b = blockIdx.z;
    const float* Ag = g_S  + (size_t)b * T_ * T_ + (size_t)blockIdx.x * BM * K;
    const float* Bg = g_VP + (size_t)b * T_ * D_;
    float*       Cg = out  + (size_t)b * T_ * D_;

    __shared__ float As[BK][BM + PAD];
    __shared__ float Bs[BK][BN + PAD];

    const int tid = threadIdx.x;
    const int bn  = blockIdx.y * BN;
    const int tx  = tid & 15;
    const int ty  = tid >> 4;

    float acc[8][8];
#pragma unroll
    for (int i = 0; i < 8; i++)
#pragma unroll
        for (int j = 0; j < 8; j++) acc[i][j] = 0.f;

    for (int k0 = 0; k0 < K; k0 += BK) {
        // A tile: 128 rows x 16 k (K-contiguous), transposed into As
#pragma unroll
        for (int i = 0; i < 2; i++) {
            int idx = tid + i * NT;
            int r = idx >> 2;
            int c = (idx & 3) * 4;
            float4 a = *(const float4*)(Ag + (size_t)r * K + k0 + c);
            As[c + 0][r] = a.x; As[c + 1][r] = a.y;
            As[c + 2][r] = a.z; As[c + 3][r] = a.w;
        }
        // B tile: 16 k-rows x 128 n (N-contiguous), direct
#pragma unroll
        for (int i = 0; i < 2; i++) {
            int idx = tid + i * NT;
            int kr = idx >> 5;
            int c4 = idx & 31;
            float4 vv = *(const float4*)(Bg + (size_t)(k0 + kr) * N + bn + c4 * 4);
            *(float4*)&Bs[kr][c4 * 4] = vv;
        }
        __syncthreads();
#pragma unroll
        for (int kk = 0; kk < BK; kk++) {
            float4 a0 = *(const float4*)&As[kk][ty * 4];
            float4 a1 = *(const float4*)&As[kk][64 + ty * 4];
            float4 b0 = *(const float4*)&Bs[kk][tx * 4];
            float4 b1 = *(const float4*)&Bs[kk][64 + tx * 4];
            float ra[8] = {a0.x, a0.y, a0.z, a0.w, a1.x, a1.y, a1.z, a1.w};
            float rb[8] = {b0.x, b0.y, b0.z, b0.w, b1.x, b1.y, b1.z, b1.w};
#pragma unroll
            for (int i = 0; i < 8; i++)
#pragma unroll
                for (int j = 0; j < 8; j++)
                    acc[i][j] = fmaf(ra[i], rb[j], acc[i][j]);
        }
        __syncthreads();
    }

    const int bm = blockIdx.x * BM;
#pragma unroll
    for (int ih = 0; ih < 2; ih++) {
#pragma unroll
        for (int ii = 0; ii < 4; ii++) {
            int m = bm + ih * 64 + ty * 4 + ii;
            int ai = ih * 4 + ii;
#pragma unroll
            for (int jh = 0; jh < 2; jh++) {
                int n = bn + jh * 64 + tx * 4;
                float4 o;
                o.x = acc[ai][jh * 4 + 0];
                o.y = acc[ai][jh * 4 + 1];
                o.z = acc[ai][jh * 4 + 2];
                o.w = acc[ai][jh * 4 + 3];
                *(float4*)(Cg + (size_t)m * N + n) = o;
            }
        }
    }
}

// ---------------------------------------------------------------------------
// Launch
// ---------------------------------------------------------------------------
extern "C" void kernel_launch(void* const* d_in, const int* in_sizes, int n_in,
                              void* d_out, int out_size)
{
    const float* q    = (const float*)d_in[0];
    const float* k    = (const float*)d_in[1];
    const float* v    = (const float*)d_in[2];
    const float* Wq   = (const float*)d_in[3];
    const float* bq   = (const float*)d_in[4];
    const float* Wk   = (const float*)d_in[5];
    const float* bk   = (const float*)d_in[6];
    const float* Wv   = (const float*)d_in[7];
    const float* bv   = (const float*)d_in[8];
    const float* mask = (const float*)d_in[9];
    float* out = (float*)d_out;

    // 1) Projections: M = B*T = 16384, N = 512
    dim3 gp((B_ * T_) / BM, D_ / BN);
    proj_kernel<<<gp, NT>>>(q, Wq, bq, 0);
    proj_kernel<<<gp, NT>>>(k, Wk, bk, 1);
    proj_kernel<<<gp, NT>>>(v, Wv, bv, 2);

    // 2) Scores (scale + mask fused in epilogue)
    dim3 gs(T_ / BM, T_ / BN, B_);
    score_kernel<<<gs, NT>>>(mask);

    // 3) Row softmax
    softmax_kernel<<<B_ * T_, NT>>>();

    // 4) O = P @ V
    dim3 go(T_ / BM, D_ / BN, B_);
    pv_kernel<<<go, NT>>>(out);
}